// round 8
// baseline (speedup 1.0000x reference)
#include <cuda_runtime.h>
#include <math.h>
#include <float.h>

#define N 256
#define NBLK 128              // 2 rows per block, single wave
#define FULL 0xffffffffu

__device__ float2 g_part[NBLK];
__device__ unsigned int g_ticket = 0;   // reset by last block each launch

// Dynamic smem: full E, 8192 float4 = 128KB, swizzled: row j chunk c at j*32+((c+j)&31)
extern __shared__ float4 sE[];

__global__ void __launch_bounds__(256, 1)
triplet_fused(const float* __restrict__ emb,
              const int*   __restrict__ lab32,
              float*       __restrict__ out) {
    __shared__ float  normsh[N];
    __shared__ float  Dmat[2 * N];
    __shared__ float  negd[2 * N];
    __shared__ float2 wpart[8];
    __shared__ int    sh_flag;

    const int t = threadIdx.x;
    const int b = blockIdx.x;
    const int w = t >> 5, l = t & 31;
    const int i0 = b * 2, i1 = i0 + 1;

    // ---- Stage E into smem with cp.async (swizzled dst, no RF round-trip).
    unsigned sb = (unsigned)__cvta_generic_to_shared(sE);
    const float4* E4 = reinterpret_cast<const float4*>(emb);
#pragma unroll
    for (int p = 0; p < 32; ++p) {
        const int g = p * 256 + t;
        const int j = g >> 5, c = g & 31;
        unsigned dst = sb + ((unsigned)((j << 5) + ((c + j) & 31)) << 4);
        asm volatile("cp.async.cg.shared.global [%0], [%1], 16;"
                     :: "r"(dst), "l"(E4 + g));
    }
    asm volatile("cp.async.commit_group;");

    // Prefetch int32-interpretation label (in-bounds for BOTH dtypes).
    const int lt32 = lab32[t];

    // Label dtype sniff (warp 0): int64 LE labels (0..15) have all-zero odd
    // 32-bit words; words [0..255] are in-bounds for both layouts.
    if (w == 0) {
        unsigned any = 0;
#pragma unroll
        for (int k = 0; k < 4; ++k)
            any |= (unsigned)lab32[2 * (l + 32 * k) + 1];
        unsigned balz = __ballot_sync(FULL, any != 0);
        if (l == 0) sh_flag = (balz != 0);
    }
    asm volatile("cp.async.wait_group 0;");
    __syncthreads();   // S1: sE + sh_flag ready

    const bool is64 = (sh_flag == 0);
    const int  labT  = is64 ? lab32[2 * t]  : lt32;
    const int  labI0 = is64 ? lab32[2 * i0] : lab32[i0];
    const int  labI1 = is64 ? lab32[2 * i1] : lab32[i1];

    // ---- Phase 1: full-row dots vs both anchors + own norm (smem only).
    const float4* rowp = sE + (t  << 5);
    const float4* rA   = sE + (i0 << 5);
    const float4* rB   = sE + (i1 << 5);
    float d0a = 0.f, d0b = 0.f, d1a = 0.f, d1b = 0.f, na = 0.f, nb = 0.f;
#pragma unroll
    for (int c = 0; c < 32; c += 2) {
        float4 bv = rowp[(c + t)  & 31];    // conflict-free (swizzle)
        float4 a0 = rA[(c + i0) & 31];      // uniform addr -> broadcast
        float4 a1 = rB[(c + i1) & 31];
        d0a += bv.x*a0.x + bv.y*a0.y + bv.z*a0.z + bv.w*a0.w;
        d1a += bv.x*a1.x + bv.y*a1.y + bv.z*a1.z + bv.w*a1.w;
        na  += bv.x*bv.x + bv.y*bv.y + bv.z*bv.z + bv.w*bv.w;
        float4 bw = rowp[(c + 1 + t)  & 31];
        float4 b0 = rA[(c + 1 + i0) & 31];
        float4 b1 = rB[(c + 1 + i1) & 31];
        d0b += bw.x*b0.x + bw.y*b0.y + bw.z*b0.z + bw.w*b0.w;
        d1b += bw.x*b1.x + bw.y*b1.y + bw.z*b1.z + bw.w*b1.w;
        nb  += bw.x*bw.x + bw.y*bw.y + bw.z*bw.z + bw.w*bw.w;
    }
    const float nt = na + nb;
    normsh[t] = nt;
    __syncthreads();   // S2: anchor norms visible

    // ---- Phase 2: distances, masks (ballots stay in registers per warp).
    const float dot0 = d0a + d0b, dot1 = d1a + d1b;
    const float D0 = sqrtf(fmaxf(normsh[i0] + nt - 2.f * dot0, 1e-4f));
    const float D1 = sqrtf(fmaxf(normsh[i1] + nt - 2.f * dot1, 1e-4f));
    const bool p0 = (labT == labI0) && (t != i0);
    const bool p1 = (labT == labI1) && (t != i1);
    Dmat[t]     = D0;  Dmat[N + t] = D1;
    // negatives include t==i (reference's (1-pos) keeps diagonal; d_ii=0.01)
    negd[t]     = p0 ? -FLT_MAX : D0;
    negd[N + t] = p1 ? -FLT_MAX : D1;
    const unsigned bal0 = __ballot_sync(FULL, p0);
    const unsigned bal1 = __ballot_sync(FULL, p1);
    __syncthreads();   // S3: Dmat/negd ready

    // ---- Phase 3: warp w handles positives among ITS OWN 32 columns.
    float lsum = 0.f;
    const float lcnt = (float)(__popc(bal0) + __popc(bal1));
#pragma unroll
    for (int r = 0; r < 2; ++r) {
        unsigned m = r ? bal1 : bal0;      // uniform across the warp
        if (!m) continue;
        const float* nd = negd + r * N;
        float v[8];
#pragma unroll
        for (int u = 0; u < 8; ++u) v[u] = nd[u * 32 + l];
        // row max over negatives (pair-independent): compute once
        float mx = v[0];
#pragma unroll
        for (int u = 1; u < 8; ++u) mx = fmaxf(mx, v[u]);
#pragma unroll
        for (int s = 16; s > 0; s >>= 1)
            mx = fmaxf(mx, __shfl_down_sync(FULL, mx, s));   // lane0-valid
        const float* Dm = Dmat + r * N + (w << 5);
        while (m) {
            const int k1 = __ffs(m) - 1;  m &= m - 1;
            const bool has2 = (m != 0);
            const int k2 = has2 ? (__ffs(m) - 1) : k1;
            if (has2) m &= m - 1;
            const float Dk1 = Dm[k1];
            const float Dk2 = Dm[k2];
            float n1a = FLT_MAX, n1b = FLT_MAX, n2a = FLT_MAX, n2b = FLT_MAX;
#pragma unroll
            for (int u = 0; u < 8; u += 2) {
                n1a = fminf(n1a, v[u]     > Dk1 ? v[u]     : FLT_MAX);
                n1b = fminf(n1b, v[u + 1] > Dk1 ? v[u + 1] : FLT_MAX);
                n2a = fminf(n2a, v[u]     > Dk2 ? v[u]     : FLT_MAX);
                n2b = fminf(n2b, v[u + 1] > Dk2 ? v[u + 1] : FLT_MAX);
            }
            float mn1 = fminf(n1a, n1b);
            float mn2 = fminf(n2a, n2b);
#pragma unroll
            for (int s = 16; s > 0; s >>= 1) {   // two chains overlap
                mn1 = fminf(mn1, __shfl_down_sync(FULL, mn1, s));
                mn2 = fminf(mn2, __shfl_down_sync(FULL, mn2, s));
            }
            if (l == 0) {
                // semi-hard if strictly-farther negative exists, else easiest
                float s1 = (mn1 < FLT_MAX) ? (Dk1 - mn1) : (Dk1 - mx);
                lsum += fmaxf(s1 + 1.0f, 0.f);          // relu(semi + MARGIN)
                if (has2) {
                    float s2 = (mn2 < FLT_MAX) ? (Dk2 - mn2) : (Dk2 - mx);
                    lsum += fmaxf(s2 + 1.0f, 0.f);
                }
            }
        }
    }
    if (l == 0) wpart[w] = make_float2(lsum, lcnt);
    __syncthreads();   // S4 (last barrier)

    // ---- Ticket + finisher: warp 0 only, no more barriers.
    if (w == 0) {
        int last = 0;
        if (l == 0) {
            float S = 0.f, C = 0.f;
#pragma unroll
            for (int k = 0; k < 8; ++k) { S += wpart[k].x; C += wpart[k].y; }
            g_part[b] = make_float2(S, C);
            unsigned tk, one = 1u;
            asm volatile("atom.acq_rel.gpu.global.add.u32 %0, [%1], %2;"
                         : "=r"(tk) : "l"(&g_ticket), "r"(one) : "memory");
            last = (tk == NBLK - 1);
            if (last) g_ticket = 0;   // all increments done; replay-safe
        }
        last = __shfl_sync(FULL, last, 0);
        if (last) {
            float S = 0.f, C = 0.f;
#pragma unroll
            for (int u = 0; u < 4; ++u) {
                float2 p = __ldcg(&g_part[l + 32 * u]);   // L2-direct
                S += p.x; C += p.y;
            }
#pragma unroll
            for (int s = 16; s > 0; s >>= 1) {
                S += __shfl_down_sync(FULL, S, s);
                C += __shfl_down_sync(FULL, C, s);
            }
            if (l == 0) out[0] = S / C;
        }
    }
}

extern "C" void kernel_launch(void* const* d_in, const int* in_sizes, int n_in,
                              void* d_out, int out_size) {
    const float* emb  = (const float*)d_in[0];
    const int*   labs = (const int*)d_in[1];
    float* out = (float*)d_out;
    cudaFuncSetAttribute(triplet_fused,
                         cudaFuncAttributeMaxDynamicSharedMemorySize, 131072);
    triplet_fused<<<NBLK, 256, 131072>>>(emb, labs, out);
}

// round 9
// speedup vs baseline: 1.0076x; 1.0076x over previous
#include <cuda_runtime.h>
#include <math.h>
#include <float.h>

#define N 256
#define RPB 4
#define NBLK (N / RPB)        // 64 blocks, single wave
#define FULL 0xffffffffu

__device__ float2 g_part[NBLK];
__device__ unsigned int g_ticket = 0;   // reset by last block each launch

// Dynamic smem: full E, 8192 float4 = 128KB, swizzled: row j chunk c at j*32+((c+j)&31)
extern __shared__ float4 sE[];

__global__ void __launch_bounds__(256, 1)
triplet_fused(const float* __restrict__ emb,
              const int*   __restrict__ lab32,
              float*       __restrict__ out) {
    __shared__ float  normsh[N];
    __shared__ float  negd[RPB * N];
    __shared__ float2 wpart[8];
    __shared__ int    sh_flag;

    const int t = threadIdx.x;
    const int b = blockIdx.x;
    const int w = t >> 5, l = t & 31;
    const int ib = b * RPB;

    // ---- Stage E into smem with cp.async (swizzled dst, no RF round-trip).
    unsigned sb = (unsigned)__cvta_generic_to_shared(sE);
    const float4* E4 = reinterpret_cast<const float4*>(emb);
#pragma unroll
    for (int p = 0; p < 32; ++p) {
        const int g = p * 256 + t;
        const int j = g >> 5, c = g & 31;
        unsigned dst = sb + ((unsigned)((j << 5) + ((c + j) & 31)) << 4);
        asm volatile("cp.async.cg.shared.global [%0], [%1], 16;"
                     :: "r"(dst), "l"(E4 + g));
    }
    asm volatile("cp.async.commit_group;");

    // Prefetch int32-interpretation label (in-bounds for BOTH dtypes).
    const int lt32 = lab32[t];

    // Label dtype sniff (warp 0): int64 LE labels (0..15) have all-zero odd
    // 32-bit words; words [0..255] are in-bounds for both layouts.
    if (w == 0) {
        unsigned any = 0;
#pragma unroll
        for (int k = 0; k < 4; ++k)
            any |= (unsigned)lab32[2 * (l + 32 * k) + 1];
        unsigned balz = __ballot_sync(FULL, any != 0);
        if (l == 0) sh_flag = (balz != 0);
    }
    asm volatile("cp.async.wait_group 0;");
    __syncthreads();   // S1: sE + sh_flag ready

    const bool is64 = (sh_flag == 0);
    const int labT = is64 ? lab32[2 * t] : lt32;
    int labI[RPB];
#pragma unroll
    for (int r = 0; r < RPB; ++r)
        labI[r] = is64 ? lab32[2 * (ib + r)] : lab32[ib + r];

    // ---- Phase 1: full-row dots vs 4 anchors + own norm (smem only).
    const float4* rowp = sE + (t << 5);
    const float4* rA0  = sE + ((ib + 0) << 5);
    const float4* rA1  = sE + ((ib + 1) << 5);
    const float4* rA2  = sE + ((ib + 2) << 5);
    const float4* rA3  = sE + ((ib + 3) << 5);
    float s0 = 0.f, s1 = 0.f, s2 = 0.f, s3 = 0.f;
    float u0 = 0.f, u1 = 0.f, u2 = 0.f, u3 = 0.f;
    float na = 0.f, nb = 0.f;
#pragma unroll
    for (int c = 0; c < 32; c += 2) {
        float4 bv = rowp[(c + t) & 31];             // conflict-free (swizzle)
        float4 a0 = rA0[(c + ib + 0) & 31];         // uniform -> broadcast
        float4 a1 = rA1[(c + ib + 1) & 31];
        float4 a2 = rA2[(c + ib + 2) & 31];
        float4 a3 = rA3[(c + ib + 3) & 31];
        s0 += bv.x*a0.x + bv.y*a0.y + bv.z*a0.z + bv.w*a0.w;
        s1 += bv.x*a1.x + bv.y*a1.y + bv.z*a1.z + bv.w*a1.w;
        s2 += bv.x*a2.x + bv.y*a2.y + bv.z*a2.z + bv.w*a2.w;
        s3 += bv.x*a3.x + bv.y*a3.y + bv.z*a3.z + bv.w*a3.w;
        na += bv.x*bv.x + bv.y*bv.y + bv.z*bv.z + bv.w*bv.w;
        float4 bw = rowp[(c + 1 + t) & 31];
        float4 b0 = rA0[(c + 1 + ib + 0) & 31];
        float4 b1 = rA1[(c + 1 + ib + 1) & 31];
        float4 b2 = rA2[(c + 1 + ib + 2) & 31];
        float4 b3 = rA3[(c + 1 + ib + 3) & 31];
        u0 += bw.x*b0.x + bw.y*b0.y + bw.z*b0.z + bw.w*b0.w;
        u1 += bw.x*b1.x + bw.y*b1.y + bw.z*b1.z + bw.w*b1.w;
        u2 += bw.x*b2.x + bw.y*b2.y + bw.z*b2.z + bw.w*b2.w;
        u3 += bw.x*b3.x + bw.y*b3.y + bw.z*b3.z + bw.w*b3.w;
        nb += bw.x*bw.x + bw.y*bw.y + bw.z*bw.z + bw.w*bw.w;
    }
    const float nt = na + nb;
    normsh[t] = nt;
    __syncthreads();   // S2: anchor norms visible

    // ---- Phase 2: distances, masks (ballots + D stay in registers).
    float dot[RPB] = { s0 + u0, s1 + u1, s2 + u2, s3 + u3 };
    float Dr[RPB];
    unsigned bal[RPB];
    int npos = 0;
#pragma unroll
    for (int r = 0; r < RPB; ++r) {
        const int i = ib + r;
        Dr[r] = sqrtf(fmaxf(normsh[i] + nt - 2.f * dot[r], 1e-4f));
        const bool pr = (labT == labI[r]) && (t != i);
        // negatives include t==i (reference's (1-pos) keeps diagonal; d_ii=0.01)
        negd[r * N + t] = pr ? -FLT_MAX : Dr[r];
        bal[r] = __ballot_sync(FULL, pr);
        npos += __popc(bal[r]);
    }
    __syncthreads();   // S3: negd ready

    // ---- Phase 3: warp w handles positives among ITS OWN 32 columns.
    // Anchor distance for column w*32+k lives in lane k's Dr -> shuffle, no smem.
    float lsum = 0.f;
    const float lcnt = (float)npos;
#pragma unroll
    for (int r = 0; r < RPB; ++r) {
        unsigned m = bal[r];               // uniform across the warp
        if (!m) continue;
        const float* nd = negd + r * N;
        float v[8];
#pragma unroll
        for (int u = 0; u < 8; ++u) v[u] = nd[u * 32 + l];
        float mx = v[0];                   // row max (pair-independent)
#pragma unroll
        for (int u = 1; u < 8; ++u) mx = fmaxf(mx, v[u]);
#pragma unroll
        for (int s = 16; s > 0; s >>= 1)
            mx = fmaxf(mx, __shfl_down_sync(FULL, mx, s));   // lane0-valid
        while (m) {
            const int k1 = __ffs(m) - 1;  m &= m - 1;
            const bool has2 = (m != 0);
            const int k2 = has2 ? (__ffs(m) - 1) : k1;
            if (has2) m &= m - 1;
            const float Dk1 = __shfl_sync(FULL, Dr[r], k1);
            const float Dk2 = __shfl_sync(FULL, Dr[r], k2);
            float n1a = FLT_MAX, n1b = FLT_MAX, n2a = FLT_MAX, n2b = FLT_MAX;
#pragma unroll
            for (int u = 0; u < 8; u += 2) {
                n1a = fminf(n1a, v[u]     > Dk1 ? v[u]     : FLT_MAX);
                n1b = fminf(n1b, v[u + 1] > Dk1 ? v[u + 1] : FLT_MAX);
                n2a = fminf(n2a, v[u]     > Dk2 ? v[u]     : FLT_MAX);
                n2b = fminf(n2b, v[u + 1] > Dk2 ? v[u + 1] : FLT_MAX);
            }
            float mn1 = fminf(n1a, n1b);
            float mn2 = fminf(n2a, n2b);
#pragma unroll
            for (int s = 16; s > 0; s >>= 1) {   // two chains overlap
                mn1 = fminf(mn1, __shfl_down_sync(FULL, mn1, s));
                mn2 = fminf(mn2, __shfl_down_sync(FULL, mn2, s));
            }
            if (l == 0) {
                // semi-hard if strictly-farther negative exists, else easiest
                float e1 = (mn1 < FLT_MAX) ? (Dk1 - mn1) : (Dk1 - mx);
                lsum += fmaxf(e1 + 1.0f, 0.f);          // relu(semi + MARGIN)
                if (has2) {
                    float e2 = (mn2 < FLT_MAX) ? (Dk2 - mn2) : (Dk2 - mx);
                    lsum += fmaxf(e2 + 1.0f, 0.f);
                }
            }
        }
    }
    if (l == 0) wpart[w] = make_float2(lsum, lcnt);
    __syncthreads();   // S4 (last barrier)

    // ---- Ticket + finisher: warp 0 only, no more barriers.
    if (w == 0) {
        int last = 0;
        if (l == 0) {
            float S = 0.f, C = 0.f;
#pragma unroll
            for (int k = 0; k < 8; ++k) { S += wpart[k].x; C += wpart[k].y; }
            g_part[b] = make_float2(S, C);
            unsigned tk, one = 1u;
            asm volatile("atom.acq_rel.gpu.global.add.u32 %0, [%1], %2;"
                         : "=r"(tk) : "l"(&g_ticket), "r"(one) : "memory");
            last = (tk == NBLK - 1);
            if (last) g_ticket = 0;   // all increments done; replay-safe
        }
        last = __shfl_sync(FULL, last, 0);
        if (last) {
            float2 pa = __ldcg(&g_part[l]);        // L2-direct
            float2 pb = __ldcg(&g_part[l + 32]);
            float S = pa.x + pb.x, C = pa.y + pb.y;
#pragma unroll
            for (int s = 16; s > 0; s >>= 1) {
                S += __shfl_down_sync(FULL, S, s);
                C += __shfl_down_sync(FULL, C, s);
            }
            if (l == 0) out[0] = S / C;
        }
    }
}

extern "C" void kernel_launch(void* const* d_in, const int* in_sizes, int n_in,
                              void* d_out, int out_size) {
    const float* emb  = (const float*)d_in[0];
    const int*   labs = (const int*)d_in[1];
    float* out = (float*)d_out;
    cudaFuncSetAttribute(triplet_fused,
                         cudaFuncAttributeMaxDynamicSharedMemorySize, 131072);
    triplet_fused<<<NBLK, 256, 131072>>>(emb, labs, out);
}

// round 11
// speedup vs baseline: 1.1662x; 1.1574x over previous
#include <cuda_runtime.h>
#include <math.h>
#include <float.h>

#define N 256
#define NBLK 128              // 2 rows per block, single wave
#define FULL 0xffffffffu

__device__ float2 g_part[NBLK];
__device__ unsigned int g_ticket = 0;   // reset by last block each launch

// Dynamic smem: full E, 8192 float4 = 128KB, swizzled: row j chunk c at j*32+((c+j)&31)
extern __shared__ float4 sE[];

__global__ void __launch_bounds__(256, 1)
triplet_fused(const float* __restrict__ emb,
              const int*   __restrict__ lab32,
              float*       __restrict__ out) {
    __shared__ float  normsh[N];
    __shared__ float  Dmat[2 * N];
    __shared__ float  negd[2 * N];
    __shared__ unsigned short pairs[2 * N];
    __shared__ int    cnts[16];
    __shared__ float  wsum[8];
    __shared__ int    sh_flag;

    const int t = threadIdx.x;
    const int b = blockIdx.x;
    const int w = t >> 5, l = t & 31;
    const int i0 = b * 2, i1 = i0 + 1;

    // ---- Stage E into smem (plain LDG+STS, swizzled dst) — R5 exact.
    const float4* E4 = reinterpret_cast<const float4*>(emb);
#pragma unroll
    for (int p = 0; p < 32; ++p) {
        const int g = p * 256 + t;
        const int j = g >> 5, c = g & 31;
        sE[(j << 5) + ((c + j) & 31)] = E4[g];
    }

    // ---- Label dtype sniff (warp 0, ballot — no init barrier needed).
    // int64 LE labels (0..15) have all-zero odd 32-bit words; words [0..255]
    // are in-bounds for both layouts.
    if (w == 0) {
        unsigned any = 0;
#pragma unroll
        for (int k = 0; k < 4; ++k)
            any |= (unsigned)lab32[2 * (l + 32 * k) + 1];
        unsigned balz = __ballot_sync(FULL, any != 0);
        if (l == 0) sh_flag = (balz != 0);
    }
    __syncthreads();   // S1: sE + sh_flag ready

    const bool is64 = (sh_flag == 0);
    const int labT  = is64 ? lab32[2 * t]  : lab32[t];
    const int labI0 = is64 ? lab32[2 * i0] : lab32[i0];
    const int labI1 = is64 ? lab32[2 * i1] : lab32[i1];

    // ---- Phase 1: full-row dots vs both anchors + own norm (smem only).
    const float4* rowp = sE + (t  << 5);
    const float4* rA   = sE + (i0 << 5);
    const float4* rB   = sE + (i1 << 5);
    float d0a = 0.f, d0b = 0.f, d1a = 0.f, d1b = 0.f, na = 0.f, nb = 0.f;
#pragma unroll
    for (int c = 0; c < 32; c += 2) {
        float4 bv = rowp[(c + t)  & 31];    // conflict-free (swizzle)
        float4 a0 = rA[(c + i0) & 31];      // uniform addr -> broadcast
        float4 a1 = rB[(c + i1) & 31];
        d0a += bv.x*a0.x + bv.y*a0.y + bv.z*a0.z + bv.w*a0.w;
        d1a += bv.x*a1.x + bv.y*a1.y + bv.z*a1.z + bv.w*a1.w;
        na  += bv.x*bv.x + bv.y*bv.y + bv.z*bv.z + bv.w*bv.w;
        float4 bw = rowp[(c + 1 + t)  & 31];
        float4 b0 = rA[(c + 1 + i0) & 31];
        float4 b1 = rB[(c + 1 + i1) & 31];
        d0b += bw.x*b0.x + bw.y*b0.y + bw.z*b0.z + bw.w*b0.w;
        d1b += bw.x*b1.x + bw.y*b1.y + bw.z*b1.z + bw.w*b1.w;
        nb  += bw.x*bw.x + bw.y*bw.y + bw.z*bw.z + bw.w*bw.w;
    }
    const float nt = na + nb;
    normsh[t] = nt;
    __syncthreads();   // S2: anchor norms visible

    // ---- Phase 2: distances, masks, per-warp counts.
    const float dot0 = d0a + d0b, dot1 = d1a + d1b;
    const float D0 = sqrtf(fmaxf(normsh[i0] + nt - 2.f * dot0, 1e-4f));
    const float D1 = sqrtf(fmaxf(normsh[i1] + nt - 2.f * dot1, 1e-4f));
    const bool p0 = (labT == labI0) && (t != i0);
    const bool p1 = (labT == labI1) && (t != i1);
    Dmat[t]     = D0;  Dmat[N + t] = D1;
    // negatives include t==i (reference's (1-pos) keeps diagonal; d_ii=0.01)
    negd[t]     = p0 ? -FLT_MAX : D0;
    negd[N + t] = p1 ? -FLT_MAX : D1;
    const unsigned bal0 = __ballot_sync(FULL, p0);
    const unsigned bal1 = __ballot_sync(FULL, p1);
    if (l == 0) { cnts[w] = __popc(bal0); cnts[8 + w] = __popc(bal1); }
    __syncthreads();   // S3: Dmat/negd/cnts ready

    // ---- In-warp redundant prefix scan of the 16 counts (no extra barrier).
    int x = (l < 16) ? cnts[l] : 0;
    const int v0 = x;
#pragma unroll
    for (int d = 1; d < 16; d <<= 1) {
        int y = __shfl_up_sync(FULL, x, d);
        if (l >= d) x += y;
    }
    const int exc = x - v0;                     // exclusive offset at slot l
    const int npair = __shfl_sync(FULL, x, 15); // total positives (uniform)
    const int off0 = __shfl_sync(FULL, exc, w);      // slot w     (r=0)
    const int off1 = __shfl_sync(FULL, exc, 8 + w);  // slot 8+w   (r=1)
    const unsigned lm = (1u << l) - 1u;
    if (p0) pairs[off0 + __popc(bal0 & lm)] = (unsigned short)t;
    if (p1) pairs[off1 + __popc(bal1 & lm)] = (unsigned short)(256 | t);
    __syncthreads();   // S4: pairs ready

    // ---- Phase 3: one warp per positive pair (R5 structure).
    float lsum = 0.f;
    for (int p = w; p < npair; p += 8) {
        const unsigned pr = pairs[p];
        const int r = pr >> 8, k = pr & 255;
        const float Dk = Dmat[r * N + k];
        const float* nd = negd + r * N;
        float mx = -FLT_MAX, mn = FLT_MAX;
#pragma unroll
        for (int u = 0; u < 8; ++u) {
            float vv = nd[u * 32 + l];
            mx = fmaxf(mx, vv);
            mn = fminf(mn, vv > Dk ? vv : FLT_MAX);
        }
#pragma unroll
        for (int s = 16; s > 0; s >>= 1) {   // two chains overlap
            mx = fmaxf(mx, __shfl_down_sync(FULL, mx, s));
            mn = fminf(mn, __shfl_down_sync(FULL, mn, s));
        }
        if (l == 0) {
            // semi-hard if strictly-farther negative exists, else easiest neg
            float semi = (mn < FLT_MAX) ? (Dk - mn) : (Dk - mx);
            lsum += fmaxf(semi + 1.0f, 0.f);   // relu(semi + MARGIN)
        }
    }
    if (l == 0) wsum[w] = lsum;
    __syncthreads();   // S5 (last barrier)

    // ---- Ticket + finisher: warp 0 only, no more barriers, no fence.
    if (w == 0) {
        int last = 0;
        if (l == 0) {
            float S = 0.f;
#pragma unroll
            for (int k = 0; k < 8; ++k) S += wsum[k];
            g_part[b] = make_float2(S, (float)npair);
            unsigned tk, one = 1u;
            asm volatile("atom.acq_rel.gpu.global.add.u32 %0, [%1], %2;"
                         : "=r"(tk) : "l"(&g_ticket), "r"(one) : "memory");
            last = (tk == NBLK - 1);
            if (last) g_ticket = 0;   // all increments done; replay-safe
        }
        last = __shfl_sync(FULL, last, 0);
        if (last) {
            float S = 0.f, C = 0.f;
#pragma unroll
            for (int u = 0; u < 4; ++u) {
                float2 p = __ldcg(&g_part[l + 32 * u]);   // L2-direct
                S += p.x; C += p.y;
            }
#pragma unroll
            for (int s = 16; s > 0; s >>= 1) {
                S += __shfl_down_sync(FULL, S, s);
                C += __shfl_down_sync(FULL, C, s);
            }
            if (l == 0) out[0] = S / C;
        }
    }
}

extern "C" void kernel_launch(void* const* d_in, const int* in_sizes, int n_in,
                              void* d_out, int out_size) {
    const float* emb  = (const float*)d_in[0];
    const int*   labs = (const int*)d_in[1];
    float* out = (float*)d_out;
    cudaFuncSetAttribute(triplet_fused,
                         cudaFuncAttributeMaxDynamicSharedMemorySize, 131072);
    triplet_fused<<<NBLK, 256, 131072>>>(emb, labs, out);
}